// round 7
// baseline (speedup 1.0000x reference)
#include <cuda_runtime.h>
#include <cuda_bf16.h>
#include <cstdint>

#define BB 2
#define HH 32
#define SS 16384
#define DD 64
#define NHEADS (BB*HH)
#define SPLIT 32
#define CHUNK (SS/SPLIT)   /* 512 s-rows per phase1 CTA */

/* phase2 config */
#define TM 128                        /* s-rows per tile */
#define NTILES (NHEADS * (SS / TM))   /* 8192 */
#define TIT 8                         /* tiles per CTA */
#define GRID2 (NTILES / TIT)          /* 1024 */

/* scratch (no runtime alloc) */
__device__ float g_part[(size_t)NHEADS * SPLIT * 4160];
__device__ float g_norm[(size_t)NHEADS * 64];
__device__ __nv_bfloat16 g_memT_hi[(size_t)NHEADS * 4096];  /* [head][dv*64+dk] */
__device__ __nv_bfloat16 g_memT_lo[(size_t)NHEADS * 4096];

__device__ __forceinline__ float elu1(float x) {
    return x > 0.0f ? x + 1.0f : __expf(x);
}

/* ---- warp-level tensor core primitives (baseline PTX) ---- */
__device__ __forceinline__ uint32_t smem_u32(const void* p) {
    uint32_t a;
    asm("{ .reg .u64 t; cvta.to.shared.u64 t, %1; cvt.u32.u64 %0, t; }" : "=r"(a) : "l"(p));
    return a;
}
__device__ __forceinline__ void ldsm_x4(uint32_t& r0, uint32_t& r1, uint32_t& r2,
                                        uint32_t& r3, uint32_t addr) {
    asm volatile("ldmatrix.sync.aligned.m8n8.x4.shared.b16 {%0,%1,%2,%3}, [%4];"
                 : "=r"(r0), "=r"(r1), "=r"(r2), "=r"(r3) : "r"(addr));
}
__device__ __forceinline__ void ldsm_x4_t(uint32_t& r0, uint32_t& r1, uint32_t& r2,
                                          uint32_t& r3, uint32_t addr) {
    asm volatile("ldmatrix.sync.aligned.m8n8.x4.trans.shared.b16 {%0,%1,%2,%3}, [%4];"
                 : "=r"(r0), "=r"(r1), "=r"(r2), "=r"(r3) : "r"(addr));
}
__device__ __forceinline__ void mma_bf16(float* d, const uint32_t* a,
                                         uint32_t b0, uint32_t b1) {
    asm volatile(
        "mma.sync.aligned.m16n8k16.row.col.f32.bf16.bf16.f32 "
        "{%0,%1,%2,%3}, {%4,%5,%6,%7}, {%8,%9}, {%0,%1,%2,%3};"
        : "+f"(d[0]), "+f"(d[1]), "+f"(d[2]), "+f"(d[3])
        : "r"(a[0]), "r"(a[1]), "r"(a[2]), "r"(a[3]), "r"(b0), "r"(b1));
}

/* swizzled byte offset: 128B rows, 16B units XOR'ed by row&7 */
#define ASWZ(row, unit) (((uint32_t)(row) << 7) + ((((unit) ^ ((row) & 7)) & 7) << 4))

/* split fp32 -> (bf16 hi, bf16 lo) packed writers */
__device__ __forceinline__ void split_store(char* hi, char* lo, float4 v,
                                            uint32_t off) {
    __nv_bfloat16 hx = __float2bfloat16(v.x), hy = __float2bfloat16(v.y);
    __nv_bfloat16 hz = __float2bfloat16(v.z), hw = __float2bfloat16(v.w);
    __nv_bfloat16 lx = __float2bfloat16(v.x - __bfloat162float(hx));
    __nv_bfloat16 ly = __float2bfloat16(v.y - __bfloat162float(hy));
    __nv_bfloat16 lz = __float2bfloat16(v.z - __bfloat162float(hz));
    __nv_bfloat16 lw = __float2bfloat16(v.w - __bfloat162float(hw));
    uint2 hp, lp;
    hp.x = (uint32_t)__bfloat16_as_ushort(hx) | ((uint32_t)__bfloat16_as_ushort(hy) << 16);
    hp.y = (uint32_t)__bfloat16_as_ushort(hz) | ((uint32_t)__bfloat16_as_ushort(hw) << 16);
    lp.x = (uint32_t)__bfloat16_as_ushort(lx) | ((uint32_t)__bfloat16_as_ushort(ly) << 16);
    lp.y = (uint32_t)__bfloat16_as_ushort(lz) | ((uint32_t)__bfloat16_as_ushort(lw) << 16);
    *(uint2*)(hi + off) = hp;
    *(uint2*)(lo + off) = lp;
}
__device__ __forceinline__ float2 bf2f(uint32_t u) {
    __nv_bfloat162 b = *(__nv_bfloat162*)&u;
    return __bfloat1622float2(b);
}

/* ============ Phase 1: memory matrix via mma.sync (trans loads) ============ */
__global__ void __launch_bounds__(128) phase1_mma(const float* __restrict__ kk,
                                                  const float* __restrict__ vv) {
    __shared__ __align__(128) char sKH[8192];
    __shared__ __align__(128) char sKL[8192];
    __shared__ __align__(128) char sVH[8192];
    __shared__ __align__(128) char sVL[8192];
    __shared__ float s_nrm[128][4];

    const int bx    = blockIdx.x;
    const int head  = bx / SPLIT;
    const int chunk = bx % SPLIT;
    const int tid   = threadIdx.x;
    const int wid   = tid >> 5;
    const int lane  = tid & 31;

    const uint32_t aKH = smem_u32(sKH), aKL = smem_u32(sKL);
    const uint32_t aVH = smem_u32(sVH), aVL = smem_u32(sVL);

    const float* kbase = kk + ((size_t)head * SS + (size_t)chunk * CHUNK) * DD;
    const float* vbase = vv + ((size_t)head * SS + (size_t)chunk * CHUNK) * DD;

    float acc[8][4] = {};      /* warp m-tile (16 dk) x 64 dv */
    float nrm[4]    = {};      /* per-thread partial, fixed 4 dk columns */
    const int myc4  = (tid & 15) * 4;

    for (int it = 0; it < CHUNK / 64; ++it) {
        __syncthreads();
        /* stage 64 s-rows of K (elu + split) and V (split), coalesced */
        #pragma unroll
        for (int p = 0; p < 8; ++p) {
            int f = tid + p * 128;             /* float4 index 0..1023 */
            int r = f >> 4;
            int c4 = (f & 15) * 4;
            uint32_t off = ASWZ(r, c4 >> 3) + ((c4 >> 2) & 1) * 8;
            float4 kf = *(const float4*)(kbase + (size_t)(it * 64 + r) * DD + c4);
            kf.x = elu1(kf.x); kf.y = elu1(kf.y); kf.z = elu1(kf.z); kf.w = elu1(kf.w);
            nrm[0] += kf.x; nrm[1] += kf.y; nrm[2] += kf.z; nrm[3] += kf.w;
            split_store(sKH, sKL, kf, off);
            float4 vf = *(const float4*)(vbase + (size_t)(it * 64 + r) * DD + c4);
            split_store(sVH, sVL, vf, off);
        }
        __syncthreads();

        /* mma: D[dk, dv] += kf^T @ v ; 3 passes (hh, hl, lh) */
        #pragma unroll
        for (int ps = 0; ps < 3; ++ps) {
            const uint32_t ab = (ps == 2) ? aKL : aKH;
            const uint32_t bb = (ps == 1) ? aVL : aVH;
            #pragma unroll
            for (int kt = 0; kt < 4; ++kt) {
                uint32_t a[4];
                {   /* A = K^T fragment via ldmatrix.trans */
                    int ar = kt * 16 + (lane & 7) + ((lane >> 4) << 3);
                    int au = wid * 2 + ((lane >> 3) & 1);
                    ldsm_x4_t(a[0], a[1], a[2], a[3], ab + ASWZ(ar, au));
                }
                uint32_t b[8][2];
                #pragma unroll
                for (int np = 0; np < 4; ++np) {
                    int br = kt * 16 + (lane & 7) + (((lane >> 3) & 1) << 3);
                    int bu = np * 2 + (lane >> 4);
                    uint32_t r0, r1, r2, r3;
                    ldsm_x4_t(r0, r1, r2, r3, bb + ASWZ(br, bu));
                    b[np*2+0][0] = r0; b[np*2+0][1] = r1;
                    b[np*2+1][0] = r2; b[np*2+1][1] = r3;
                }
                #pragma unroll
                for (int nt = 0; nt < 8; ++nt)
                    mma_bf16(acc[nt], a, b[nt][0], b[nt][1]);
            }
        }
    }

    /* write M partial: rows = dk (warp m-tile), cols = dv */
    float* outp = g_part + (size_t)bx * 4160;
    {
        int r_lo = wid * 16 + (lane >> 2);
        int r_hi = r_lo + 8;
        int c0   = (lane & 3) * 2;
        #pragma unroll
        for (int nt = 0; nt < 8; ++nt) {
            *(float2*)&outp[r_lo * 64 + nt * 8 + c0] = make_float2(acc[nt][0], acc[nt][1]);
            *(float2*)&outp[r_hi * 64 + nt * 8 + c0] = make_float2(acc[nt][2], acc[nt][3]);
        }
    }
    /* norm: deterministic reduction across the 8 threads per column group */
    s_nrm[tid][0] = nrm[0]; s_nrm[tid][1] = nrm[1];
    s_nrm[tid][2] = nrm[2]; s_nrm[tid][3] = nrm[3];
    __syncthreads();
    if (tid < 16) {
        float s0 = 0.f, s1 = 0.f, s2 = 0.f, s3 = 0.f;
        #pragma unroll
        for (int g = 0; g < 8; ++g) {
            s0 += s_nrm[tid + 16*g][0]; s1 += s_nrm[tid + 16*g][1];
            s2 += s_nrm[tid + 16*g][2]; s3 += s_nrm[tid + 16*g][3];
        }
        *(float4*)&outp[4096 + tid * 4] = make_float4(s0, s1, s2, s3);
    }
}

/* ------- Reduce: sum SPLIT partials; emit transposed bf16 hi/lo + fp32 norm ------- */
__global__ void __launch_bounds__(512) reduce_k() {
    const int head = blockIdx.x;
    for (int e = threadIdx.x; e < 4160; e += 512) {
        float s = 0.f;
        #pragma unroll 8
        for (int c = 0; c < SPLIT; ++c)
            s += g_part[((size_t)head * SPLIT + c) * 4160 + e];
        if (e < 4096) {
            int dk = e >> 6, dv = e & 63;
            __nv_bfloat16 h = __float2bfloat16(s);
            __nv_bfloat16 l = __float2bfloat16(s - __bfloat162float(h));
            g_memT_hi[(size_t)head * 4096 + dv * 64 + dk] = h;
            g_memT_lo[(size_t)head * 4096 + dv * 64 + dk] = l;
        } else {
            g_norm[(size_t)head * 64 + (e - 4096)] = s;
        }
    }
}

/* ============ Phase 2: retrieval GEMM, coalesced staging, 256 thr ============ */
#define SM_AH 0
#define SM_AL 16384
#define SM_BH 32768
#define SM_BL 40960
#define SM_DYN_TOTAL 49152

__global__ void __launch_bounds__(256) phase2_mma(const float* __restrict__ q,
                                                  float* __restrict__ outg) {
    extern __shared__ __align__(128) char dyn[];

    const int tid  = threadIdx.x;
    const int wid  = tid >> 5;        /* 0..7, warp m-tile = rows wid*16.. */
    const int lane = tid & 31;
    const uint32_t sb = smem_u32(dyn);

    const int t0   = blockIdx.x * TIT;
    const int head = t0 >> 7;

    /* ---- per-CTA: memory matrix (bf16 hi/lo, swizzled) ---- */
    {
        const __nv_bfloat16* bh = g_memT_hi + (size_t)head * 4096;
        const __nv_bfloat16* bl = g_memT_lo + (size_t)head * 4096;
        #pragma unroll
        for (int p = 0; p < 2; ++p) {
            int f = tid + p * 256;         /* 16B-unit 0..511 */
            int r = f >> 3;
            int u = f & 7;
            uint32_t off = ASWZ(r, u);
            *(uint4*)(dyn + SM_BH + off) = *(const uint4*)(bh + r * 64 + u * 8);
            *(uint4*)(dyn + SM_BL + off) = *(const uint4*)(bl + r * 64 + u * 8);
        }
    }

    const float* nrm = g_norm + (size_t)head * 64;

    for (int it = 0; it < TIT; ++it) {
        const int t  = t0 + it;
        const int s0 = (t & 127) * TM;

        __syncthreads();   /* previous tile's ldsm/den reads done before overwrite */

        /* ---- coalesced Q staging: elu + bf16 split ---- */
        const float* qb = q + ((size_t)head * SS + (size_t)s0) * DD;
        #pragma unroll
        for (int p = 0; p < 8; ++p) {
            int f = tid + p * 256;         /* float4 index 0..2047 */
            int r = f >> 4;
            int c4 = (f & 15) * 4;
            float4 v = *(const float4*)(qb + (size_t)r * DD + c4);
            v.x = elu1(v.x); v.y = elu1(v.y); v.z = elu1(v.z); v.w = elu1(v.w);
            uint32_t off = ASWZ(r, c4 >> 3) + ((c4 >> 2) & 1) * 8;
            split_store(dyn + SM_AH, dyn + SM_AL, v, off);
        }
        __syncthreads();

        /* ---- denominator: lanes 0..15 of each warp handle that warp's rows ---- */
        float den = 0.f;
        if (lane < 16) {
            int row = wid * 16 + lane;
            #pragma unroll
            for (int u = 0; u < 8; ++u) {
                uint4 h = *(uint4*)(dyn + SM_AH + ASWZ(row, u));
                uint4 l = *(uint4*)(dyn + SM_AL + ASWZ(row, u));
                const float* np = nrm + u * 8;
                float2 f0 = bf2f(h.x), g0 = bf2f(l.x);
                float2 f1 = bf2f(h.y), g1 = bf2f(l.y);
                float2 f2 = bf2f(h.z), g2 = bf2f(l.z);
                float2 f3 = bf2f(h.w), g3 = bf2f(l.w);
                den += (f0.x + g0.x) * __ldg(np+0) + (f0.y + g0.y) * __ldg(np+1)
                     + (f1.x + g1.x) * __ldg(np+2) + (f1.y + g1.y) * __ldg(np+3)
                     + (f2.x + g2.x) * __ldg(np+4) + (f2.y + g2.y) * __ldg(np+5)
                     + (f3.x + g3.x) * __ldg(np+6) + (f3.y + g3.y) * __ldg(np+7);
            }
        }

        /* ---- 3-pass bf16 mma: hh + hl + lh ---- */
        float acc[8][4];
        #pragma unroll
        for (int nt = 0; nt < 8; ++nt)
            #pragma unroll
            for (int e = 0; e < 4; ++e) acc[nt][e] = 0.f;

        #pragma unroll
        for (int ps = 0; ps < 3; ++ps) {
            const uint32_t abase = sb + ((ps == 2) ? SM_AL : SM_AH);
            const uint32_t bbase = sb + ((ps == 1) ? SM_BL : SM_BH);
            #pragma unroll
            for (int kt = 0; kt < 4; ++kt) {
                uint32_t a[4];
                {
                    int ar = wid * 16 + (lane & 15);
                    ldsm_x4(a[0], a[1], a[2], a[3],
                            abase + ASWZ(ar, kt * 2 + (lane >> 4)));
                }
                uint32_t b[8][2];
                #pragma unroll
                for (int np = 0; np < 4; ++np) {
                    int br = np * 16 + (lane & 7) + ((lane >> 4) << 3);
                    uint32_t r0, r1, r2, r3;
                    ldsm_x4(r0, r1, r2, r3,
                            bbase + ASWZ(br, kt * 2 + ((lane >> 3) & 1)));
                    b[np*2+0][0] = r0; b[np*2+0][1] = r1;
                    b[np*2+1][0] = r2; b[np*2+1][1] = r3;
                }
                #pragma unroll
                for (int nt = 0; nt < 8; ++nt)
                    mma_bf16(acc[nt], a, b[nt][0], b[nt][1]);
            }
        }

        /* ---- epilogue: den via shuffle, divide, store ---- */
        float inv_lo = 1.0f / __shfl_sync(0xffffffffu, den, lane >> 2);
        float inv_hi = 1.0f / __shfl_sync(0xffffffffu, den, (lane >> 2) + 8);
        float* obase = outg + ((size_t)head * SS + (size_t)s0) * DD;
        int r_lo = wid * 16 + (lane >> 2);
        int r_hi = r_lo + 8;
        int c0   = (lane & 3) * 2;
        #pragma unroll
        for (int nt = 0; nt < 8; ++nt) {
            *(float2*)(obase + (size_t)r_lo * DD + nt * 8 + c0) =
                make_float2(acc[nt][0] * inv_lo, acc[nt][1] * inv_lo);
            *(float2*)(obase + (size_t)r_hi * DD + nt * 8 + c0) =
                make_float2(acc[nt][2] * inv_hi, acc[nt][3] * inv_hi);
        }
    }
}

extern "C" void kernel_launch(void* const* d_in, const int* in_sizes, int n_in,
                              void* d_out, int out_size) {
    const float* q = (const float*)d_in[0];
    const float* k = (const float*)d_in[1];
    const float* v = (const float*)d_in[2];
    float* out = (float*)d_out;

    cudaFuncSetAttribute(phase2_mma, cudaFuncAttributeMaxDynamicSharedMemorySize,
                         SM_DYN_TOTAL);

    phase1_mma<<<NHEADS * SPLIT, 128>>>(k, v);
    reduce_k<<<NHEADS, 512>>>();
    phase2_mma<<<GRID2, 256, SM_DYN_TOTAL>>>(q, out);
}

// round 8
// speedup vs baseline: 1.4376x; 1.4376x over previous
#include <cuda_runtime.h>
#include <cuda_bf16.h>
#include <cstdint>

#define BB 2
#define HH 32
#define SS 16384
#define DD 64
#define NHEADS (BB*HH)
#define SPLIT 16
#define CHUNK (SS/SPLIT)   /* 1024 s-rows per phase1 CTA */

/* phase2 config */
#define TM 64                         /* s-rows per tile */
#define TILES_PER_HEAD (SS / TM)      /* 256 */
#define TIT 16                        /* tiles per CTA */
#define GRID2 (NHEADS * TILES_PER_HEAD / TIT)  /* 1024 */

/* scratch (no runtime alloc) */
__device__ float g_part[(size_t)NHEADS * SPLIT * 4160];
__device__ float g_norm[(size_t)NHEADS * 64];
__device__ __nv_bfloat16 g_memT_hi[(size_t)NHEADS * 4096];  /* [head][dv*64+dk] */
__device__ __nv_bfloat16 g_memT_lo[(size_t)NHEADS * 4096];

__device__ __forceinline__ float elu1(float x) {
    return x > 0.0f ? x + 1.0f : __expf(x);
}

__device__ __forceinline__ uint32_t smem_u32(const void* p) {
    uint32_t a;
    asm("{ .reg .u64 t; cvta.to.shared.u64 t, %1; cvt.u32.u64 %0, t; }" : "=r"(a) : "l"(p));
    return a;
}
__device__ __forceinline__ void ldsm_x4(uint32_t& r0, uint32_t& r1, uint32_t& r2,
                                        uint32_t& r3, uint32_t addr) {
    asm volatile("ldmatrix.sync.aligned.m8n8.x4.shared.b16 {%0,%1,%2,%3}, [%4];"
                 : "=r"(r0), "=r"(r1), "=r"(r2), "=r"(r3) : "r"(addr));
}
__device__ __forceinline__ void ldsm_x4_t(uint32_t& r0, uint32_t& r1, uint32_t& r2,
                                          uint32_t& r3, uint32_t addr) {
    asm volatile("ldmatrix.sync.aligned.m8n8.x4.trans.shared.b16 {%0,%1,%2,%3}, [%4];"
                 : "=r"(r0), "=r"(r1), "=r"(r2), "=r"(r3) : "r"(addr));
}
__device__ __forceinline__ void mma_bf16(float* d, const uint32_t* a,
                                         uint32_t b0, uint32_t b1) {
    asm volatile(
        "mma.sync.aligned.m16n8k16.row.col.f32.bf16.bf16.f32 "
        "{%0,%1,%2,%3}, {%4,%5,%6,%7}, {%8,%9}, {%0,%1,%2,%3};"
        : "+f"(d[0]), "+f"(d[1]), "+f"(d[2]), "+f"(d[3])
        : "r"(a[0]), "r"(a[1]), "r"(a[2]), "r"(a[3]), "r"(b0), "r"(b1));
}

/* swizzled byte offset: 128B rows, 16B units XOR'ed by row&7 */
#define ASWZ(row, unit) (((uint32_t)(row) << 7) + ((((unit) ^ ((row) & 7)) & 7) << 4))

__device__ __forceinline__ void split_store(char* hi, char* lo, float4 v,
                                            uint32_t off) {
    __nv_bfloat16 hx = __float2bfloat16(v.x), hy = __float2bfloat16(v.y);
    __nv_bfloat16 hz = __float2bfloat16(v.z), hw = __float2bfloat16(v.w);
    __nv_bfloat16 lx = __float2bfloat16(v.x - __bfloat162float(hx));
    __nv_bfloat16 ly = __float2bfloat16(v.y - __bfloat162float(hy));
    __nv_bfloat16 lz = __float2bfloat16(v.z - __bfloat162float(hz));
    __nv_bfloat16 lw = __float2bfloat16(v.w - __bfloat162float(hw));
    uint2 hp, lp;
    hp.x = (uint32_t)__bfloat16_as_ushort(hx) | ((uint32_t)__bfloat16_as_ushort(hy) << 16);
    hp.y = (uint32_t)__bfloat16_as_ushort(hz) | ((uint32_t)__bfloat16_as_ushort(hw) << 16);
    lp.x = (uint32_t)__bfloat16_as_ushort(lx) | ((uint32_t)__bfloat16_as_ushort(ly) << 16);
    lp.y = (uint32_t)__bfloat16_as_ushort(lz) | ((uint32_t)__bfloat16_as_ushort(lw) << 16);
    *(uint2*)(hi + off) = hp;
    *(uint2*)(lo + off) = lp;
}
__device__ __forceinline__ float2 bf2f(uint32_t u) {
    __nv_bfloat162 b = *(__nv_bfloat162*)&u;
    return __bfloat1622float2(b);
}

/* ============ Phase 1: M = kf^T @ v via mma.sync, 8 warps / 4x2 split ============ */
__global__ void __launch_bounds__(256, 3)
phase1_mma(const float* __restrict__ kk, const float* __restrict__ vv) {
    __shared__ __align__(128) char sKH[8192];
    __shared__ __align__(128) char sKL[8192];
    __shared__ __align__(128) char sVH[8192];
    __shared__ __align__(128) char sVL[8192];
    __shared__ float s_nrm[256][4];

    const int bx    = blockIdx.x;
    const int head  = bx / SPLIT;
    const int chunk = bx % SPLIT;
    const int tid   = threadIdx.x;
    const int wid   = tid >> 5;
    const int lane  = tid & 31;
    const int mi    = wid >> 1;       /* dk m-tile 0..3 */
    const int nh    = wid & 1;        /* dv half 0..1 */

    const uint32_t aKH = smem_u32(sKH), aKL = smem_u32(sKL);
    const uint32_t aVH = smem_u32(sVH), aVL = smem_u32(sVL);

    const float* kbase = kk + ((size_t)head * SS + (size_t)chunk * CHUNK) * DD;
    const float* vbase = vv + ((size_t)head * SS + (size_t)chunk * CHUNK) * DD;

    float acc[4][4] = {};    /* m-tile (16 dk) x 32 dv */
    float nrm[4]    = {};    /* per-thread, columns (tid&15)*4 .. +3 */

    for (int it = 0; it < CHUNK / 64; ++it) {
        __syncthreads();
        #pragma unroll
        for (int p = 0; p < 4; ++p) {
            int f = tid + p * 256;             /* float4 index 0..1023 */
            int r = f >> 4;
            int c4 = (f & 15) * 4;
            uint32_t off = ASWZ(r, c4 >> 3) + ((c4 >> 2) & 1) * 8;
            float4 kf = *(const float4*)(kbase + (size_t)(it * 64 + r) * DD + c4);
            kf.x = elu1(kf.x); kf.y = elu1(kf.y); kf.z = elu1(kf.z); kf.w = elu1(kf.w);
            nrm[0] += kf.x; nrm[1] += kf.y; nrm[2] += kf.z; nrm[3] += kf.w;
            split_store(sKH, sKL, kf, off);
            float4 vf = *(const float4*)(vbase + (size_t)(it * 64 + r) * DD + c4);
            split_store(sVH, sVL, vf, off);
        }
        __syncthreads();

        #pragma unroll
        for (int ps = 0; ps < 3; ++ps) {
            const uint32_t ab = (ps == 2) ? aKL : aKH;
            const uint32_t bb = (ps == 1) ? aVL : aVH;
            #pragma unroll
            for (int kt = 0; kt < 4; ++kt) {
                uint32_t a[4];
                {
                    int ar = kt * 16 + (lane & 7) + ((lane >> 4) << 3);
                    int au = mi * 2 + ((lane >> 3) & 1);
                    ldsm_x4_t(a[0], a[1], a[2], a[3], ab + ASWZ(ar, au));
                }
                uint32_t b[4][2];
                #pragma unroll
                for (int np = 0; np < 2; ++np) {
                    int br = kt * 16 + (lane & 7) + (((lane >> 3) & 1) << 3);
                    int bu = nh * 4 + np * 2 + (lane >> 4);
                    uint32_t r0, r1, r2, r3;
                    ldsm_x4_t(r0, r1, r2, r3, bb + ASWZ(br, bu));
                    b[np*2+0][0] = r0; b[np*2+0][1] = r1;
                    b[np*2+1][0] = r2; b[np*2+1][1] = r3;
                }
                #pragma unroll
                for (int nt = 0; nt < 4; ++nt)
                    mma_bf16(acc[nt], a, b[nt][0], b[nt][1]);
            }
        }
    }

    /* write M partial: rows = dk (m-tile mi), cols = dv (half nh) */
    float* outp = g_part + (size_t)bx * 4160;
    {
        int r_lo = mi * 16 + (lane >> 2);
        int r_hi = r_lo + 8;
        int c0   = nh * 32 + (lane & 3) * 2;
        #pragma unroll
        for (int nt = 0; nt < 4; ++nt) {
            *(float2*)&outp[r_lo * 64 + nt * 8 + c0] = make_float2(acc[nt][0], acc[nt][1]);
            *(float2*)&outp[r_hi * 64 + nt * 8 + c0] = make_float2(acc[nt][2], acc[nt][3]);
        }
    }
    /* norm: deterministic cross-thread reduction */
    s_nrm[tid][0] = nrm[0]; s_nrm[tid][1] = nrm[1];
    s_nrm[tid][2] = nrm[2]; s_nrm[tid][3] = nrm[3];
    __syncthreads();
    if (tid < 16) {
        float s0 = 0.f, s1 = 0.f, s2 = 0.f, s3 = 0.f;
        #pragma unroll
        for (int g = 0; g < 16; ++g) {
            s0 += s_nrm[tid + 16*g][0]; s1 += s_nrm[tid + 16*g][1];
            s2 += s_nrm[tid + 16*g][2]; s3 += s_nrm[tid + 16*g][3];
        }
        *(float4*)&outp[4096 + tid * 4] = make_float4(s0, s1, s2, s3);
    }
}

/* ------- Reduce: sum SPLIT partials; emit transposed bf16 hi/lo + fp32 norm ------- */
__global__ void __launch_bounds__(512) reduce_k() {
    const int head = blockIdx.x;
    for (int e = threadIdx.x; e < 4160; e += 512) {
        float s = 0.f;
        #pragma unroll
        for (int c = 0; c < SPLIT; ++c)
            s += g_part[((size_t)head * SPLIT + c) * 4160 + e];
        if (e < 4096) {
            int dk = e >> 6, dv = e & 63;
            __nv_bfloat16 h = __float2bfloat16(s);
            __nv_bfloat16 l = __float2bfloat16(s - __bfloat162float(h));
            g_memT_hi[(size_t)head * 4096 + dv * 64 + dk] = h;
            g_memT_lo[(size_t)head * 4096 + dv * 64 + dk] = l;
        } else {
            g_norm[(size_t)head * 64 + (e - 4096)] = s;
        }
    }
}

/* ============ Phase 2: Out = Qf @ M^T via mma.sync, TM=64, 8 warps / 4x2 ============ */
__global__ void __launch_bounds__(256, 3)
phase2_mma(const float* __restrict__ q, float* __restrict__ outg) {
    __shared__ __align__(128) char sAH[8192];
    __shared__ __align__(128) char sAL[8192];
    __shared__ __align__(128) char sBH[8192];
    __shared__ __align__(128) char sBL[8192];
    __shared__ float sden[64];

    const int tid  = threadIdx.x;
    const int wid  = tid >> 5;
    const int lane = tid & 31;
    const int mi   = wid >> 1;        /* m-tile 0..3 (rows mi*16..) */
    const int nh   = wid & 1;         /* n-half 0..1 (dv nh*32..) */

    const uint32_t aAH = smem_u32(sAH), aAL = smem_u32(sAL);
    const uint32_t aBH = smem_u32(sBH), aBL = smem_u32(sBL);

    const int t0   = blockIdx.x * TIT;
    const int head = t0 / TILES_PER_HEAD;   /* constant per CTA (TIT | 256) */

    /* ---- per-CTA: memory matrix (bf16 hi/lo, swizzled) ---- */
    {
        const __nv_bfloat16* bh = g_memT_hi + (size_t)head * 4096;
        const __nv_bfloat16* bl = g_memT_lo + (size_t)head * 4096;
        #pragma unroll
        for (int p = 0; p < 2; ++p) {
            int f = tid + p * 256;         /* 16B-unit 0..511 */
            int r = f >> 3;
            int u = f & 7;
            uint32_t off = ASWZ(r, u);
            *(uint4*)(sBH + off) = *(const uint4*)(bh + r * 64 + u * 8);
            *(uint4*)(sBL + off) = *(const uint4*)(bl + r * 64 + u * 8);
        }
    }

    const float* nrm = g_norm + (size_t)head * 64;

    for (int it = 0; it < TIT; ++it) {
        const int s0 = ((t0 + it) % TILES_PER_HEAD) * TM;

        __syncthreads();   /* prior tile done reading A/sden */

        /* ---- coalesced Q staging: elu + bf16 split ---- */
        const float* qb = q + ((size_t)head * SS + (size_t)s0) * DD;
        #pragma unroll
        for (int p = 0; p < 4; ++p) {
            int f = tid + p * 256;         /* float4 index 0..1023 */
            int r = f >> 4;
            int c4 = (f & 15) * 4;
            float4 v = *(const float4*)(qb + (size_t)r * DD + c4);
            v.x = elu1(v.x); v.y = elu1(v.y); v.z = elu1(v.z); v.w = elu1(v.w);
            uint32_t off = ASWZ(r, c4 >> 3) + ((c4 >> 2) & 1) * 8;
            split_store(sAH, sAL, v, off);
        }
        __syncthreads();

        /* ---- denominator: 64 threads, one row each (bounded unroll) ---- */
        if (lane < 8) {
            int row = wid * 8 + lane;
            float den = 0.f;
            #pragma unroll 2
            for (int u = 0; u < 8; ++u) {
                uint4 h = *(uint4*)(sAH + ASWZ(row, u));
                uint4 l = *(uint4*)(sAL + ASWZ(row, u));
                const float* np = nrm + u * 8;
                float2 f0 = bf2f(h.x), g0 = bf2f(l.x);
                float2 f1 = bf2f(h.y), g1 = bf2f(l.y);
                float2 f2 = bf2f(h.z), g2 = bf2f(l.z);
                float2 f3 = bf2f(h.w), g3 = bf2f(l.w);
                den += (f0.x + g0.x) * __ldg(np+0) + (f0.y + g0.y) * __ldg(np+1)
                     + (f1.x + g1.x) * __ldg(np+2) + (f1.y + g1.y) * __ldg(np+3)
                     + (f2.x + g2.x) * __ldg(np+4) + (f2.y + g2.y) * __ldg(np+5)
                     + (f3.x + g3.x) * __ldg(np+6) + (f3.y + g3.y) * __ldg(np+7);
            }
            sden[row] = den;
        }

        /* ---- 3-pass bf16 mma: hh + hl + lh ---- */
        float acc[4][4];
        #pragma unroll
        for (int nt = 0; nt < 4; ++nt)
            #pragma unroll
            for (int e = 0; e < 4; ++e) acc[nt][e] = 0.f;

        #pragma unroll
        for (int ps = 0; ps < 3; ++ps) {
            const uint32_t abase = (ps == 2) ? aAL : aAH;
            const uint32_t bbase = (ps == 1) ? aBL : aBH;
            #pragma unroll
            for (int kt = 0; kt < 4; ++kt) {
                uint32_t a[4];
                {
                    int ar = mi * 16 + (lane & 15);
                    ldsm_x4(a[0], a[1], a[2], a[3],
                            abase + ASWZ(ar, kt * 2 + (lane >> 4)));
                }
                uint32_t b[4][2];
                #pragma unroll
                for (int np = 0; np < 2; ++np) {
                    int br = nh * 32 + np * 16 + (lane & 7) + ((lane >> 4) << 3);
                    uint32_t r0, r1, r2, r3;
                    ldsm_x4(r0, r1, r2, r3,
                            bbase + ASWZ(br, kt * 2 + ((lane >> 3) & 1)));
                    b[np*2+0][0] = r0; b[np*2+0][1] = r1;
                    b[np*2+1][0] = r2; b[np*2+1][1] = r3;
                }
                #pragma unroll
                for (int nt = 0; nt < 4; ++nt)
                    mma_bf16(acc[nt], a, b[nt][0], b[nt][1]);
            }
        }

        __syncthreads();   /* sden complete; A reads done */

        /* ---- epilogue: divide, store ---- */
        int r_lo = mi * 16 + (lane >> 2);
        int r_hi = r_lo + 8;
        float inv_lo = 1.0f / sden[r_lo];
        float inv_hi = 1.0f / sden[r_hi];
        float* obase = outg + ((size_t)head * SS + (size_t)s0) * DD;
        int c0 = nh * 32 + (lane & 3) * 2;
        #pragma unroll
        for (int nt = 0; nt < 4; ++nt) {
            *(float2*)(obase + (size_t)r_lo * DD + nt * 8 + c0) =
                make_float2(acc[nt][0] * inv_lo, acc[nt][1] * inv_lo);
            *(float2*)(obase + (size_t)r_hi * DD + nt * 8 + c0) =
                make_float2(acc[nt][2] * inv_hi, acc[nt][3] * inv_hi);
        }
    }
}

extern "C" void kernel_launch(void* const* d_in, const int* in_sizes, int n_in,
                              void* d_out, int out_size) {
    const float* q = (const float*)d_in[0];
    const float* k = (const float*)d_in[1];
    const float* v = (const float*)d_in[2];
    float* out = (float*)d_out;

    phase1_mma<<<NHEADS * SPLIT, 256>>>(k, v);
    reduce_k<<<NHEADS, 512>>>();
    phase2_mma<<<GRID2, 256>>>(q, out);
}

// round 9
// speedup vs baseline: 1.9949x; 1.3876x over previous
#include <cuda_runtime.h>
#include <cuda_bf16.h>
#include <cstdint>

#define BB 2
#define HH 32
#define SS 16384
#define DD 64
#define NHEADS (BB*HH)
#define SPLIT 16
#define CHUNK (SS/SPLIT)   /* 1024 s-rows per phase1 CTA */
#define NIT (CHUNK/64)     /* 16 staging iterations */

/* phase2 config */
#define TM 64                         /* s-rows per tile */
#define TILES_PER_HEAD (SS / TM)      /* 256 */
#define TIT 16                        /* tiles per CTA */
#define GRID2 (NHEADS * TILES_PER_HEAD / TIT)  /* 1024 */

/* scratch (no runtime alloc) */
__device__ float g_part[(size_t)NHEADS * SPLIT * 4160];
__device__ float g_norm[(size_t)NHEADS * 64];
__device__ __nv_bfloat16 g_memT_hi[(size_t)NHEADS * 4096];  /* [head][dv*64+dk] */
__device__ __nv_bfloat16 g_memT_lo[(size_t)NHEADS * 4096];

__device__ __forceinline__ float elu1(float x) {
    return x > 0.0f ? x + 1.0f : __expf(x);
}

__device__ __forceinline__ uint32_t smem_u32(const void* p) {
    uint32_t a;
    asm("{ .reg .u64 t; cvta.to.shared.u64 t, %1; cvt.u32.u64 %0, t; }" : "=r"(a) : "l"(p));
    return a;
}
__device__ __forceinline__ void ldsm_x4(uint32_t& r0, uint32_t& r1, uint32_t& r2,
                                        uint32_t& r3, uint32_t addr) {
    asm volatile("ldmatrix.sync.aligned.m8n8.x4.shared.b16 {%0,%1,%2,%3}, [%4];"
                 : "=r"(r0), "=r"(r1), "=r"(r2), "=r"(r3) : "r"(addr));
}
__device__ __forceinline__ void ldsm_x4_t(uint32_t& r0, uint32_t& r1, uint32_t& r2,
                                          uint32_t& r3, uint32_t addr) {
    asm volatile("ldmatrix.sync.aligned.m8n8.x4.trans.shared.b16 {%0,%1,%2,%3}, [%4];"
                 : "=r"(r0), "=r"(r1), "=r"(r2), "=r"(r3) : "r"(addr));
}
__device__ __forceinline__ void mma_bf16(float* d, const uint32_t* a,
                                         uint32_t b0, uint32_t b1) {
    asm volatile(
        "mma.sync.aligned.m16n8k16.row.col.f32.bf16.bf16.f32 "
        "{%0,%1,%2,%3}, {%4,%5,%6,%7}, {%8,%9}, {%0,%1,%2,%3};"
        : "+f"(d[0]), "+f"(d[1]), "+f"(d[2]), "+f"(d[3])
        : "r"(a[0]), "r"(a[1]), "r"(a[2]), "r"(a[3]), "r"(b0), "r"(b1));
}

/* swizzled byte offset: 128B rows, 16B units XOR'ed by row&7 */
#define ASWZ(row, unit) (((uint32_t)(row) << 7) + ((((unit) ^ ((row) & 7)) & 7) << 4))

__device__ __forceinline__ void split_store(char* hi, char* lo, float4 v,
                                            uint32_t off) {
    __nv_bfloat16 hx = __float2bfloat16(v.x), hy = __float2bfloat16(v.y);
    __nv_bfloat16 hz = __float2bfloat16(v.z), hw = __float2bfloat16(v.w);
    __nv_bfloat16 lx = __float2bfloat16(v.x - __bfloat162float(hx));
    __nv_bfloat16 ly = __float2bfloat16(v.y - __bfloat162float(hy));
    __nv_bfloat16 lz = __float2bfloat16(v.z - __bfloat162float(hz));
    __nv_bfloat16 lw = __float2bfloat16(v.w - __bfloat162float(hw));
    uint2 hp, lp;
    hp.x = (uint32_t)__bfloat16_as_ushort(hx) | ((uint32_t)__bfloat16_as_ushort(hy) << 16);
    hp.y = (uint32_t)__bfloat16_as_ushort(hz) | ((uint32_t)__bfloat16_as_ushort(hw) << 16);
    lp.x = (uint32_t)__bfloat16_as_ushort(lx) | ((uint32_t)__bfloat16_as_ushort(ly) << 16);
    lp.y = (uint32_t)__bfloat16_as_ushort(lz) | ((uint32_t)__bfloat16_as_ushort(lw) << 16);
    *(uint2*)(hi + off) = hp;
    *(uint2*)(lo + off) = lp;
}
__device__ __forceinline__ float2 bf2f(uint32_t u) {
    __nv_bfloat162 b = *(__nv_bfloat162*)&u;
    return __bfloat1622float2(b);
}

/* ============ Phase 1: M = kf^T @ v via mma.sync, pipelined staging ============ */
__global__ void __launch_bounds__(256, 2)
phase1_mma(const float* __restrict__ kk, const float* __restrict__ vv) {
    __shared__ __align__(128) char sKH[8192];
    __shared__ __align__(128) char sKL[8192];
    __shared__ __align__(128) char sVH[8192];
    __shared__ __align__(128) char sVL[8192];
    __shared__ float s_nrm[256][4];

    const int bx    = blockIdx.x;
    const int head  = bx / SPLIT;
    const int chunk = bx % SPLIT;
    const int tid   = threadIdx.x;
    const int wid   = tid >> 5;
    const int lane  = tid & 31;
    const int mi    = wid >> 1;       /* dk m-tile 0..3 */
    const int nh    = wid & 1;        /* dv half 0..1 */

    const uint32_t aKH = smem_u32(sKH), aKL = smem_u32(sKL);
    const uint32_t aVH = smem_u32(sVH), aVL = smem_u32(sVL);

    /* per-thread staging slots (fixed across iterations) */
    int srow[4]; uint32_t soff[4];
    #pragma unroll
    for (int p = 0; p < 4; ++p) {
        int f = tid + p * 256;
        srow[p] = f >> 4;
        int c4 = (f & 15) * 4;
        soff[p] = ASWZ(srow[p], c4 >> 3) + ((c4 >> 2) & 1) * 8;
    }
    const float* kbase = kk + ((size_t)head * SS + (size_t)chunk * CHUNK) * DD
                            + (size_t)((tid & 15) * 4);
    const float* vbase = vv + ((size_t)head * SS + (size_t)chunk * CHUNK) * DD
                            + (size_t)((tid & 15) * 4);

    float acc[4][4] = {};
    float nrm[4]    = {};

    float4 pk[4], pv[4];
    #pragma unroll
    for (int p = 0; p < 4; ++p) {
        pk[p] = *(const float4*)(kbase + (size_t)srow[p] * DD);
        pv[p] = *(const float4*)(vbase + (size_t)srow[p] * DD);
    }

    for (int it = 0; it < NIT; ++it) {
        __syncthreads();
        #pragma unroll
        for (int p = 0; p < 4; ++p) {
            float4 kf = pk[p];
            kf.x = elu1(kf.x); kf.y = elu1(kf.y); kf.z = elu1(kf.z); kf.w = elu1(kf.w);
            nrm[0] += kf.x; nrm[1] += kf.y; nrm[2] += kf.z; nrm[3] += kf.w;
            split_store(sKH, sKL, kf, soff[p]);
            split_store(sVH, sVL, pv[p], soff[p]);
        }
        __syncthreads();

        /* prefetch next block — LDGs in flight during the mma section */
        if (it + 1 < NIT) {
            const float* kn = kbase + (size_t)(it + 1) * 64 * DD;
            const float* vn = vbase + (size_t)(it + 1) * 64 * DD;
            #pragma unroll
            for (int p = 0; p < 4; ++p) {
                pk[p] = *(const float4*)(kn + (size_t)srow[p] * DD);
                pv[p] = *(const float4*)(vn + (size_t)srow[p] * DD);
            }
        }

        #pragma unroll
        for (int ps = 0; ps < 3; ++ps) {
            const uint32_t ab = (ps == 2) ? aKL : aKH;
            const uint32_t bb = (ps == 1) ? aVL : aVH;
            #pragma unroll
            for (int kt = 0; kt < 4; ++kt) {
                uint32_t a[4];
                {
                    int ar = kt * 16 + (lane & 7) + ((lane >> 4) << 3);
                    int au = mi * 2 + ((lane >> 3) & 1);
                    ldsm_x4_t(a[0], a[1], a[2], a[3], ab + ASWZ(ar, au));
                }
                uint32_t b[4][2];
                #pragma unroll
                for (int np = 0; np < 2; ++np) {
                    int br = kt * 16 + (lane & 7) + (((lane >> 3) & 1) << 3);
                    int bu = nh * 4 + np * 2 + (lane >> 4);
                    uint32_t r0, r1, r2, r3;
                    ldsm_x4_t(r0, r1, r2, r3, bb + ASWZ(br, bu));
                    b[np*2+0][0] = r0; b[np*2+0][1] = r1;
                    b[np*2+1][0] = r2; b[np*2+1][1] = r3;
                }
                #pragma unroll
                for (int nt = 0; nt < 4; ++nt)
                    mma_bf16(acc[nt], a, b[nt][0], b[nt][1]);
            }
        }
    }

    /* write M partial */
    float* outp = g_part + (size_t)bx * 4160;
    {
        int r_lo = mi * 16 + (lane >> 2);
        int r_hi = r_lo + 8;
        int c0   = nh * 32 + (lane & 3) * 2;
        #pragma unroll
        for (int nt = 0; nt < 4; ++nt) {
            *(float2*)&outp[r_lo * 64 + nt * 8 + c0] = make_float2(acc[nt][0], acc[nt][1]);
            *(float2*)&outp[r_hi * 64 + nt * 8 + c0] = make_float2(acc[nt][2], acc[nt][3]);
        }
    }
    /* norm: deterministic cross-thread reduction */
    s_nrm[tid][0] = nrm[0]; s_nrm[tid][1] = nrm[1];
    s_nrm[tid][2] = nrm[2]; s_nrm[tid][3] = nrm[3];
    __syncthreads();
    if (tid < 16) {
        float s0 = 0.f, s1 = 0.f, s2 = 0.f, s3 = 0.f;
        #pragma unroll
        for (int g = 0; g < 16; ++g) {
            s0 += s_nrm[tid + 16*g][0]; s1 += s_nrm[tid + 16*g][1];
            s2 += s_nrm[tid + 16*g][2]; s3 += s_nrm[tid + 16*g][3];
        }
        *(float4*)&outp[4096 + tid * 4] = make_float4(s0, s1, s2, s3);
    }
}

/* ------- Reduce: sum SPLIT partials; emit transposed bf16 hi/lo + fp32 norm ------- */
__global__ void __launch_bounds__(512) reduce_k() {
    const int head = blockIdx.x;
    for (int e = threadIdx.x; e < 4160; e += 512) {
        float s = 0.f;
        #pragma unroll
        for (int c = 0; c < SPLIT; ++c)
            s += g_part[((size_t)head * SPLIT + c) * 4160 + e];
        if (e < 4096) {
            int dk = e >> 6, dv = e & 63;
            __nv_bfloat16 h = __float2bfloat16(s);
            __nv_bfloat16 l = __float2bfloat16(s - __bfloat162float(h));
            g_memT_hi[(size_t)head * 4096 + dv * 64 + dk] = h;
            g_memT_lo[(size_t)head * 4096 + dv * 64 + dk] = l;
        } else {
            g_norm[(size_t)head * 64 + (e - 4096)] = s;
        }
    }
}

/* ============ Phase 2: Out = Qf @ M^T via mma.sync, pipelined staging ============ */
__global__ void __launch_bounds__(256, 2)
phase2_mma(const float* __restrict__ q, float* __restrict__ outg) {
    __shared__ __align__(128) char sAH[8192];
    __shared__ __align__(128) char sAL[8192];
    __shared__ __align__(128) char sBH[8192];
    __shared__ __align__(128) char sBL[8192];
    __shared__ float sden[64];

    const int tid  = threadIdx.x;
    const int wid  = tid >> 5;
    const int lane = tid & 31;
    const int mi   = wid >> 1;        /* m-tile 0..3 */
    const int nh   = wid & 1;         /* n-half 0..1 */

    const uint32_t aAH = smem_u32(sAH), aAL = smem_u32(sAL);
    const uint32_t aBH = smem_u32(sBH), aBL = smem_u32(sBL);

    const int t0   = blockIdx.x * TIT;
    const int head = t0 / TILES_PER_HEAD;

    /* ---- per-CTA: memory matrix (bf16 hi/lo, swizzled) ---- */
    {
        const __nv_bfloat16* bh = g_memT_hi + (size_t)head * 4096;
        const __nv_bfloat16* bl = g_memT_lo + (size_t)head * 4096;
        #pragma unroll
        for (int p = 0; p < 2; ++p) {
            int f = tid + p * 256;
            int r = f >> 3;
            int u = f & 7;
            uint32_t off = ASWZ(r, u);
            *(uint4*)(sBH + off) = *(const uint4*)(bh + r * 64 + u * 8);
            *(uint4*)(sBL + off) = *(const uint4*)(bl + r * 64 + u * 8);
        }
    }

    const float* nrm = g_norm + (size_t)head * 64;

    /* per-thread staging slots */
    int srow[4]; uint32_t soff[4];
    #pragma unroll
    for (int p = 0; p < 4; ++p) {
        int f = tid + p * 256;
        srow[p] = f >> 4;
        int c4 = (f & 15) * 4;
        soff[p] = ASWZ(srow[p], c4 >> 3) + ((c4 >> 2) & 1) * 8;
    }
    const float* qcol = q + ((size_t)head * SS) * DD + (size_t)((tid & 15) * 4);

    /* prefetch tile 0 */
    float4 pq[4];
    {
        const int s0 = (t0 % TILES_PER_HEAD) * TM;
        #pragma unroll
        for (int p = 0; p < 4; ++p)
            pq[p] = *(const float4*)(qcol + (size_t)(s0 + srow[p]) * DD);
    }

    for (int it = 0; it < TIT; ++it) {
        const int s0 = ((t0 + it) % TILES_PER_HEAD) * TM;

        __syncthreads();   /* prior tile done reading A/sden */

        #pragma unroll
        for (int p = 0; p < 4; ++p) {
            float4 v = pq[p];
            v.x = elu1(v.x); v.y = elu1(v.y); v.z = elu1(v.z); v.w = elu1(v.w);
            split_store(sAH, sAL, v, soff[p]);
        }
        __syncthreads();

        /* prefetch next tile — LDGs overlap den + mma + epilogue */
        if (it + 1 < TIT) {
            const int s1 = ((t0 + it + 1) % TILES_PER_HEAD) * TM;
            #pragma unroll
            for (int p = 0; p < 4; ++p)
                pq[p] = *(const float4*)(qcol + (size_t)(s1 + srow[p]) * DD);
        }

        /* ---- denominator: 64 threads, one row each ---- */
        if (lane < 8) {
            int row = wid * 8 + lane;
            float den = 0.f;
            #pragma unroll 2
            for (int u = 0; u < 8; ++u) {
                uint4 h = *(uint4*)(sAH + ASWZ(row, u));
                uint4 l = *(uint4*)(sAL + ASWZ(row, u));
                const float* np = nrm + u * 8;
                float2 f0 = bf2f(h.x), g0 = bf2f(l.x);
                float2 f1 = bf2f(h.y), g1 = bf2f(l.y);
                float2 f2 = bf2f(h.z), g2 = bf2f(l.z);
                float2 f3 = bf2f(h.w), g3 = bf2f(l.w);
                den += (f0.x + g0.x) * __ldg(np+0) + (f0.y + g0.y) * __ldg(np+1)
                     + (f1.x + g1.x) * __ldg(np+2) + (f1.y + g1.y) * __ldg(np+3)
                     + (f2.x + g2.x) * __ldg(np+4) + (f2.y + g2.y) * __ldg(np+5)
                     + (f3.x + g3.x) * __ldg(np+6) + (f3.y + g3.y) * __ldg(np+7);
            }
            sden[row] = den;
        }

        /* ---- 3-pass bf16 mma: hh + hl + lh ---- */
        float acc[4][4];
        #pragma unroll
        for (int nt = 0; nt < 4; ++nt)
            #pragma unroll
            for (int e = 0; e < 4; ++e) acc[nt][e] = 0.f;

        #pragma unroll
        for (int ps = 0; ps < 3; ++ps) {
            const uint32_t abase = (ps == 2) ? aAL : aAH;
            const uint32_t bbase = (ps == 1) ? aBL : aBH;
            #pragma unroll
            for (int kt = 0; kt < 4; ++kt) {
                uint32_t a[4];
                {
                    int ar = mi * 16 + (lane & 15);
                    ldsm_x4(a[0], a[1], a[2], a[3],
                            abase + ASWZ(ar, kt * 2 + (lane >> 4)));
                }
                uint32_t b[4][2];
                #pragma unroll
                for (int np = 0; np < 2; ++np) {
                    int br = nh * 32 + np * 16 + (lane & 7) + ((lane >> 4) << 3);
                    uint32_t r0, r1, r2, r3;
                    ldsm_x4(r0, r1, r2, r3,
                            bbase + ASWZ(br, kt * 2 + ((lane >> 3) & 1)));
                    b[np*2+0][0] = r0; b[np*2+0][1] = r1;
                    b[np*2+1][0] = r2; b[np*2+1][1] = r3;
                }
                #pragma unroll
                for (int nt = 0; nt < 4; ++nt)
                    mma_bf16(acc[nt], a, b[nt][0], b[nt][1]);
            }
        }

        __syncthreads();   /* sden complete */

        /* ---- epilogue: divide, store ---- */
        int r_lo = mi * 16 + (lane >> 2);
        int r_hi = r_lo + 8;
        float inv_lo = 1.0f / sden[r_lo];
        float inv_hi = 1.0f / sden[r_hi];
        float* obase = outg + ((size_t)head * SS + (size_t)s0) * DD;
        int c0 = nh * 32 + (lane & 3) * 2;
        #pragma unroll
        for (int nt = 0; nt < 4; ++nt) {
            *(float2*)(obase + (size_t)r_lo * DD + nt * 8 + c0) =
                make_float2(acc[nt][0] * inv_lo, acc[nt][1] * inv_lo);
            *(float2*)(obase + (size_t)r_hi * DD + nt * 8 + c0) =
                make_float2(acc[nt][2] * inv_hi, acc[nt][3] * inv_hi);
        }
    }
}

extern "C" void kernel_launch(void* const* d_in, const int* in_sizes, int n_in,
                              void* d_out, int out_size) {
    const float* q = (const float*)d_in[0];
    const float* k = (const float*)d_in[1];
    const float* v = (const float*)d_in[2];
    float* out = (float*)d_out;

    phase1_mma<<<NHEADS * SPLIT, 256>>>(k, v);
    reduce_k<<<NHEADS, 512>>>();
    phase2_mma<<<GRID2, 256>>>(q, out);
}

// round 10
// speedup vs baseline: 2.6148x; 1.3108x over previous
#include <cuda_runtime.h>
#include <cuda_bf16.h>
#include <cstdint>

#define BB 2
#define HH 32
#define SS 16384
#define DD 64
#define NHEADS (BB*HH)
#define SPLIT 16
#define CHUNK (SS/SPLIT)   /* 1024 s-rows per phase1 CTA */
#define NIT (CHUNK/64)     /* 16 staging iterations */

/* phase2 config */
#define TM 64                         /* s-rows per tile */
#define TILES_PER_HEAD (SS / TM)      /* 256 */
#define TIT 16                        /* tiles per CTA */
#define GRID2 (NHEADS * TILES_PER_HEAD / TIT)  /* 1024 */

/* scratch (no runtime alloc) */
__device__ float g_part[(size_t)NHEADS * SPLIT * 4160];
__device__ float g_norm[(size_t)NHEADS * 64];
__device__ __nv_bfloat16 g_memT_hi[(size_t)NHEADS * 4096];  /* [head][dv*64+dk] */
__device__ __nv_bfloat16 g_memT_lo[(size_t)NHEADS * 4096];

__device__ __forceinline__ float elu1(float x) {
    return x > 0.0f ? x + 1.0f : __expf(x);
}

__device__ __forceinline__ uint32_t smem_u32(const void* p) {
    uint32_t a;
    asm("{ .reg .u64 t; cvta.to.shared.u64 t, %1; cvt.u32.u64 %0, t; }" : "=r"(a) : "l"(p));
    return a;
}
__device__ __forceinline__ void ldsm_x4(uint32_t& r0, uint32_t& r1, uint32_t& r2,
                                        uint32_t& r3, uint32_t addr) {
    asm volatile("ldmatrix.sync.aligned.m8n8.x4.shared.b16 {%0,%1,%2,%3}, [%4];"
                 : "=r"(r0), "=r"(r1), "=r"(r2), "=r"(r3) : "r"(addr));
}
__device__ __forceinline__ void ldsm_x4_t(uint32_t& r0, uint32_t& r1, uint32_t& r2,
                                          uint32_t& r3, uint32_t addr) {
    asm volatile("ldmatrix.sync.aligned.m8n8.x4.trans.shared.b16 {%0,%1,%2,%3}, [%4];"
                 : "=r"(r0), "=r"(r1), "=r"(r2), "=r"(r3) : "r"(addr));
}
__device__ __forceinline__ void mma_bf16(float* d, const uint32_t* a,
                                         uint32_t b0, uint32_t b1) {
    asm volatile(
        "mma.sync.aligned.m16n8k16.row.col.f32.bf16.bf16.f32 "
        "{%0,%1,%2,%3}, {%4,%5,%6,%7}, {%8,%9}, {%0,%1,%2,%3};"
        : "+f"(d[0]), "+f"(d[1]), "+f"(d[2]), "+f"(d[3])
        : "r"(a[0]), "r"(a[1]), "r"(a[2]), "r"(a[3]), "r"(b0), "r"(b1));
}

/* swizzled byte offset: 128B rows, 16B units XOR'ed by row&7 */
#define ASWZ(row, unit) (((uint32_t)(row) << 7) + ((((unit) ^ ((row) & 7)) & 7) << 4))

/* pack (lo_val -> low half, hi_val -> high half) as bf16x2, RN rounding */
__device__ __forceinline__ uint32_t pack_bf16x2(float lo_val, float hi_val) {
    uint32_t r;
    asm("cvt.rn.bf16x2.f32 %0, %1, %2;" : "=r"(r) : "f"(hi_val), "f"(lo_val));
    return r;
}

/* split fp32x4 -> bf16 hi/lo via cvt.bf16x2 (cheap ALU path) */
__device__ __forceinline__ void split_store(char* hi, char* lo, float4 v,
                                            uint32_t off) {
    uint32_t h0 = pack_bf16x2(v.x, v.y);
    uint32_t h1 = pack_bf16x2(v.z, v.w);
    float hx = __uint_as_float(h0 << 16);
    float hy = __uint_as_float(h0 & 0xffff0000u);
    float hz = __uint_as_float(h1 << 16);
    float hw = __uint_as_float(h1 & 0xffff0000u);
    uint32_t l0 = pack_bf16x2(v.x - hx, v.y - hy);
    uint32_t l1 = pack_bf16x2(v.z - hz, v.w - hw);
    *(uint2*)(hi + off) = make_uint2(h0, h1);
    *(uint2*)(lo + off) = make_uint2(l0, l1);
}

/* ============ Phase 1: M = kf^T @ v via mma.sync, pipelined staging ============ */
__global__ void __launch_bounds__(256, 2)
phase1_mma(const float* __restrict__ kk, const float* __restrict__ vv) {
    __shared__ __align__(128) char sKH[8192];
    __shared__ __align__(128) char sKL[8192];
    __shared__ __align__(128) char sVH[8192];
    __shared__ __align__(128) char sVL[8192];
    __shared__ float s_nrm[256][4];

    const int bx    = blockIdx.x;
    const int head  = bx / SPLIT;
    const int chunk = bx % SPLIT;
    const int tid   = threadIdx.x;
    const int wid   = tid >> 5;
    const int lane  = tid & 31;
    const int mi    = wid >> 1;       /* dk m-tile 0..3 */
    const int nh    = wid & 1;        /* dv half 0..1 */

    const uint32_t aKH = smem_u32(sKH), aKL = smem_u32(sKL);
    const uint32_t aVH = smem_u32(sVH), aVL = smem_u32(sVL);

    int srow[4]; uint32_t soff[4];
    #pragma unroll
    for (int p = 0; p < 4; ++p) {
        int f = tid + p * 256;
        srow[p] = f >> 4;
        int c4 = (f & 15) * 4;
        soff[p] = ASWZ(srow[p], c4 >> 3) + ((c4 >> 2) & 1) * 8;
    }
    const float* kbase = kk + ((size_t)head * SS + (size_t)chunk * CHUNK) * DD
                            + (size_t)((tid & 15) * 4);
    const float* vbase = vv + ((size_t)head * SS + (size_t)chunk * CHUNK) * DD
                            + (size_t)((tid & 15) * 4);

    float acc[4][4] = {};
    float nrm[4]    = {};

    float4 pk[4], pv[4];
    #pragma unroll
    for (int p = 0; p < 4; ++p) {
        pk[p] = *(const float4*)(kbase + (size_t)srow[p] * DD);
        pv[p] = *(const float4*)(vbase + (size_t)srow[p] * DD);
    }

    for (int it = 0; it < NIT; ++it) {
        __syncthreads();
        #pragma unroll
        for (int p = 0; p < 4; ++p) {
            float4 kf = pk[p];
            kf.x = elu1(kf.x); kf.y = elu1(kf.y); kf.z = elu1(kf.z); kf.w = elu1(kf.w);
            nrm[0] += kf.x; nrm[1] += kf.y; nrm[2] += kf.z; nrm[3] += kf.w;
            split_store(sKH, sKL, kf, soff[p]);
            split_store(sVH, sVL, pv[p], soff[p]);
        }
        __syncthreads();

        /* prefetch next block — LDGs in flight during the mma section */
        if (it + 1 < NIT) {
            const float* kn = kbase + (size_t)(it + 1) * 64 * DD;
            const float* vn = vbase + (size_t)(it + 1) * 64 * DD;
            #pragma unroll
            for (int p = 0; p < 4; ++p) {
                pk[p] = *(const float4*)(kn + (size_t)srow[p] * DD);
                pv[p] = *(const float4*)(vn + (size_t)srow[p] * DD);
            }
        }

        #pragma unroll
        for (int ps = 0; ps < 3; ++ps) {
            const uint32_t ab = (ps == 2) ? aKL : aKH;
            const uint32_t bb = (ps == 1) ? aVL : aVH;
            #pragma unroll
            for (int kt = 0; kt < 4; ++kt) {
                uint32_t a[4];
                {
                    int ar = kt * 16 + (lane & 7) + ((lane >> 4) << 3);
                    int au = mi * 2 + ((lane >> 3) & 1);
                    ldsm_x4_t(a[0], a[1], a[2], a[3], ab + ASWZ(ar, au));
                }
                uint32_t b[4][2];
                #pragma unroll
                for (int np = 0; np < 2; ++np) {
                    int br = kt * 16 + (lane & 7) + (((lane >> 3) & 1) << 3);
                    int bu = nh * 4 + np * 2 + (lane >> 4);
                    uint32_t r0, r1, r2, r3;
                    ldsm_x4_t(r0, r1, r2, r3, bb + ASWZ(br, bu));
                    b[np*2+0][0] = r0; b[np*2+0][1] = r1;
                    b[np*2+1][0] = r2; b[np*2+1][1] = r3;
                }
                #pragma unroll
                for (int nt = 0; nt < 4; ++nt)
                    mma_bf16(acc[nt], a, b[nt][0], b[nt][1]);
            }
        }
    }

    /* write M partial */
    float* outp = g_part + (size_t)bx * 4160;
    {
        int r_lo = mi * 16 + (lane >> 2);
        int r_hi = r_lo + 8;
        int c0   = nh * 32 + (lane & 3) * 2;
        #pragma unroll
        for (int nt = 0; nt < 4; ++nt) {
            *(float2*)&outp[r_lo * 64 + nt * 8 + c0] = make_float2(acc[nt][0], acc[nt][1]);
            *(float2*)&outp[r_hi * 64 + nt * 8 + c0] = make_float2(acc[nt][2], acc[nt][3]);
        }
    }
    /* norm: deterministic cross-thread reduction */
    s_nrm[tid][0] = nrm[0]; s_nrm[tid][1] = nrm[1];
    s_nrm[tid][2] = nrm[2]; s_nrm[tid][3] = nrm[3];
    __syncthreads();
    if (tid < 16) {
        float s0 = 0.f, s1 = 0.f, s2 = 0.f, s3 = 0.f;
        #pragma unroll
        for (int g = 0; g < 16; ++g) {
            s0 += s_nrm[tid + 16*g][0]; s1 += s_nrm[tid + 16*g][1];
            s2 += s_nrm[tid + 16*g][2]; s3 += s_nrm[tid + 16*g][3];
        }
        *(float4*)&outp[4096 + tid * 4] = make_float4(s0, s1, s2, s3);
    }
}

/* ------- Reduce: sum SPLIT partials; emit transposed bf16 hi/lo + fp32 norm ------- */
__global__ void __launch_bounds__(512) reduce_k() {
    const int head = blockIdx.x;
    for (int e = threadIdx.x; e < 4160; e += 512) {
        float s = 0.f;
        #pragma unroll
        for (int c = 0; c < SPLIT; ++c)
            s += g_part[((size_t)head * SPLIT + c) * 4160 + e];
        if (e < 4096) {
            int dk = e >> 6, dv = e & 63;
            __nv_bfloat16 h = __float2bfloat16(s);
            __nv_bfloat16 l = __float2bfloat16(s - __bfloat162float(h));
            g_memT_hi[(size_t)head * 4096 + dv * 64 + dk] = h;
            g_memT_lo[(size_t)head * 4096 + dv * 64 + dk] = l;
        } else {
            g_norm[(size_t)head * 64 + (e - 4096)] = s;
        }
    }
}

/* ============ Phase 2: Out = Qf @ M^T via mma.sync, den fused into staging ============ */
__global__ void __launch_bounds__(256, 2)
phase2_mma(const float* __restrict__ q, float* __restrict__ outg) {
    __shared__ __align__(128) char sAH[8192];
    __shared__ __align__(128) char sAL[8192];
    __shared__ __align__(128) char sBH[8192];
    __shared__ __align__(128) char sBL[8192];
    __shared__ float sden[64];

    const int tid  = threadIdx.x;
    const int wid  = tid >> 5;
    const int lane = tid & 31;
    const int mi   = wid >> 1;        /* m-tile 0..3 */
    const int nh   = wid & 1;         /* n-half 0..1 */

    const uint32_t aAH = smem_u32(sAH), aAL = smem_u32(sAL);
    const uint32_t aBH = smem_u32(sBH), aBL = smem_u32(sBL);

    const int t0   = blockIdx.x * TIT;
    const int head = t0 / TILES_PER_HEAD;

    /* ---- per-CTA: memory matrix (bf16 hi/lo, swizzled) ---- */
    {
        const __nv_bfloat16* bh = g_memT_hi + (size_t)head * 4096;
        const __nv_bfloat16* bl = g_memT_lo + (size_t)head * 4096;
        #pragma unroll
        for (int p = 0; p < 2; ++p) {
            int f = tid + p * 256;
            int r = f >> 3;
            int u = f & 7;
            uint32_t off = ASWZ(r, u);
            *(uint4*)(sBH + off) = *(const uint4*)(bh + r * 64 + u * 8);
            *(uint4*)(sBL + off) = *(const uint4*)(bl + r * 64 + u * 8);
        }
    }

    /* per-thread staging slots; this thread's fixed 4 columns */
    int srow[4]; uint32_t soff[4];
    #pragma unroll
    for (int p = 0; p < 4; ++p) {
        int f = tid + p * 256;
        srow[p] = f >> 4;
        int c4 = (f & 15) * 4;
        soff[p] = ASWZ(srow[p], c4 >> 3) + ((c4 >> 2) & 1) * 8;
    }
    const float4 mynrm = *(const float4*)(g_norm + (size_t)head * 64 + (tid & 15) * 4);
    const float* qcol = q + ((size_t)head * SS) * DD + (size_t)((tid & 15) * 4);

    /* prefetch tile 0 */
    float4 pq[4];
    {
        const int s0 = (t0 % TILES_PER_HEAD) * TM;
        #pragma unroll
        for (int p = 0; p < 4; ++p)
            pq[p] = *(const float4*)(qcol + (size_t)(s0 + srow[p]) * DD);
    }

    for (int it = 0; it < TIT; ++it) {
        const int s0 = ((t0 + it) % TILES_PER_HEAD) * TM;

        __syncthreads();   /* prior tile done reading A/sden */

        /* ---- stage A + fused denominator (fp32, deterministic shfl tree) ---- */
        #pragma unroll
        for (int p = 0; p < 4; ++p) {
            float4 v = pq[p];
            v.x = elu1(v.x); v.y = elu1(v.y); v.z = elu1(v.z); v.w = elu1(v.w);
            split_store(sAH, sAL, v, soff[p]);
            float dp = v.x * mynrm.x + v.y * mynrm.y + v.z * mynrm.z + v.w * mynrm.w;
            dp += __shfl_xor_sync(0xffffffffu, dp, 1);
            dp += __shfl_xor_sync(0xffffffffu, dp, 2);
            dp += __shfl_xor_sync(0xffffffffu, dp, 4);
            dp += __shfl_xor_sync(0xffffffffu, dp, 8);
            if ((lane & 15) == 0) sden[srow[p]] = dp;
        }
        __syncthreads();

        /* prefetch next tile — LDGs overlap mma + epilogue */
        if (it + 1 < TIT) {
            const int s1 = ((t0 + it + 1) % TILES_PER_HEAD) * TM;
            #pragma unroll
            for (int p = 0; p < 4; ++p)
                pq[p] = *(const float4*)(qcol + (size_t)(s1 + srow[p]) * DD);
        }

        /* ---- 3-pass bf16 mma: hh + hl + lh ---- */
        float acc[4][4];
        #pragma unroll
        for (int nt = 0; nt < 4; ++nt)
            #pragma unroll
            for (int e = 0; e < 4; ++e) acc[nt][e] = 0.f;

        #pragma unroll
        for (int ps = 0; ps < 3; ++ps) {
            const uint32_t abase = (ps == 2) ? aAL : aAH;
            const uint32_t bbase = (ps == 1) ? aBL : aBH;
            #pragma unroll
            for (int kt = 0; kt < 4; ++kt) {
                uint32_t a[4];
                {
                    int ar = mi * 16 + (lane & 15);
                    ldsm_x4(a[0], a[1], a[2], a[3],
                            abase + ASWZ(ar, kt * 2 + (lane >> 4)));
                }
                uint32_t b[4][2];
                #pragma unroll
                for (int np = 0; np < 2; ++np) {
                    int br = nh * 32 + np * 16 + (lane & 7) + ((lane >> 4) << 3);
                    uint32_t r0, r1, r2, r3;
                    ldsm_x4(r0, r1, r2, r3,
                            bbase + ASWZ(br, kt * 2 + ((lane >> 3) & 1)));
                    b[np*2+0][0] = r0; b[np*2+0][1] = r1;
                    b[np*2+1][0] = r2; b[np*2+1][1] = r3;
                }
                #pragma unroll
                for (int nt = 0; nt < 4; ++nt)
                    mma_bf16(acc[nt], a, b[nt][0], b[nt][1]);
            }
        }

        /* ---- epilogue: divide, store (sden valid since post-staging sync) ---- */
        int r_lo = mi * 16 + (lane >> 2);
        int r_hi = r_lo + 8;
        float inv_lo = 1.0f / sden[r_lo];
        float inv_hi = 1.0f / sden[r_hi];
        float* obase = outg + ((size_t)head * SS + (size_t)s0) * DD;
        int c0 = nh * 32 + (lane & 3) * 2;
        #pragma unroll
        for (int nt = 0; nt < 4; ++nt) {
            *(float2*)(obase + (size_t)r_lo * DD + nt * 8 + c0) =
                make_float2(acc[nt][0] * inv_lo, acc[nt][1] * inv_lo);
            *(float2*)(obase + (size_t)r_hi * DD + nt * 8 + c0) =
                make_float2(acc[nt][2] * inv_hi, acc[nt][3] * inv_hi);
        }
    }
}

extern "C" void kernel_launch(void* const* d_in, const int* in_sizes, int n_in,
                              void* d_out, int out_size) {
    const float* q = (const float*)d_in[0];
    const float* k = (const float*)d_in[1];
    const float* v = (const float*)d_in[2];
    float* out = (float*)d_out;

    phase1_mma<<<NHEADS * SPLIT, 256>>>(k, v);
    reduce_k<<<NHEADS, 512>>>();
    phase2_mma<<<GRID2, 256>>>(q, out);
}